// round 3
// baseline (speedup 1.0000x reference)
#include <cuda_runtime.h>
#include <cstdint>
#include <cstddef>

// Problem constants
#define B_ 32
#define S_ 4096
#define E_ 1024
#define H_ 16
#define D_ 64
#define NSPLIT 16

// ---------------- static scratch (no runtime allocation) ----------------
__device__ float g_q[B_ * E_];                         // q = seq1@Wq + bq       [b][e]
__device__ float g_qk[B_ * H_ * E_];                   // folded q@Wk, *0.125    [b][h][e]
__device__ float g_scores[B_ * H_ * S_];               // raw scores             [b][h][s]
__device__ float g_attn[B_ * H_ * S_];                 // softmax                [b][h][s]
__device__ float g_ctxp[NSPLIT * B_ * H_ * E_];        // ctx partials           [sp][b][h][e]

typedef unsigned long long u64;

__device__ __forceinline__ u64 pack2(float x, float y) {
    u64 p;
    asm("mov.b64 %0, {%1, %2};" : "=l"(p) : "f"(x), "f"(y));
    return p;
}
__device__ __forceinline__ void unpack2(u64 p, float& x, float& y) {
    asm("mov.b64 {%0, %1}, %2;" : "=f"(x), "=f"(y) : "l"(p));
}
__device__ __forceinline__ u64 ffma2(u64 a, u64 b, u64 c) {
    u64 d;
    asm("fma.rn.f32x2 %0, %1, %2, %3;" : "=l"(d) : "l"(a), "l"(b), "l"(c));
    return d;
}

// ---------------- K1: q[b][j] = seq1[b]·Wq[:,j] + bq[j] ----------------
// grid (4, 32) block 256
__global__ void k_qproj(const float* __restrict__ seq1, const float* __restrict__ Wq,
                        const float* __restrict__ bq) {
    int b = blockIdx.y;
    int j = blockIdx.x * 256 + threadIdx.x;
    __shared__ __align__(16) float s1[E_];
    ((float4*)s1)[threadIdx.x] = ((const float4*)(seq1 + (size_t)b * E_))[threadIdx.x];
    __syncthreads();
    float acc = bq[j];
#pragma unroll 8
    for (int e = 0; e < E_; e++)
        acc = fmaf(s1[e], Wq[(size_t)e * E_ + j], acc);
    g_q[b * E_ + j] = acc;
}

// ---------------- K2: qk[b][h][e] = (Σ_d q[b][h*64+d]·Wk[e][h*64+d]) * 0.125 ----------------
// grid (16 h, 4 et) block 256, thread = e within tile
__global__ void k_qk(const float* __restrict__ Wk) {
    int h = blockIdx.x;
    int e = blockIdx.y * 256 + threadIdx.x;
    __shared__ __align__(16) float2 sq[B_][D_ / 2];   // q pairs per b for this head
    for (int i = threadIdx.x; i < B_ * (D_ / 2); i += 256) {
        int b = i >> 5, dp = i & 31;
        sq[b][dp] = ((const float2*)(g_q + b * E_ + h * D_))[dp];
    }
    __syncthreads();
    float2 wk[D_ / 2];
    const float2* wrow = (const float2*)(Wk + (size_t)e * E_ + h * D_);
#pragma unroll
    for (int i = 0; i < D_ / 2; i++) wk[i] = wrow[i];
#pragma unroll 4
    for (int b = 0; b < B_; b++) {
        float ax = 0.f, ay = 0.f;
#pragma unroll
        for (int i = 0; i < D_ / 2; i++) {
            float2 qv = sq[b][i];
            ax = fmaf(wk[i].x, qv.x, ax);
            ay = fmaf(wk[i].y, qv.y, ay);
        }
        g_qk[(b * H_ + h) * E_ + e] = (ax + ay) * 0.125f;
    }
}

// ---------------- K3: scores[b][h][s] = seq2[b,s,:]·qk[b][h][:]  (skip masked rows) ----------------
// grid (32 s-tiles of 128, 32 b) block 256
// thread: e_idx = tid>>2 (16 e-elems), h_grp = tid&3 (h = hg*4+j, j=0..3)
__global__ void __launch_bounds__(256, 2) k_scores(const float* __restrict__ seq2,
                                                   const int* __restrict__ mask) {
    int b = blockIdx.y;
    int s0 = blockIdx.x * 128;
    int tid = threadIdx.x;
    int eidx = tid >> 2;
    int hg = tid & 3;

    __shared__ __align__(16) float sx[4][E_];           // 16 KB: 4 staged rows
    __shared__ __align__(16) float spart[4][H_][68];    // 17.4 KB padded partials [r][h][eg]
    __shared__ int smask[128];

    if (tid < 128) smask[tid] = mask[b * S_ + s0 + tid];

    // qk for this thread's 4 heads x 16 e, as 8 f32x2 each
    u64 qk2[4][8];
#pragma unroll
    for (int j = 0; j < 4; j++) {
        const float4* p = (const float4*)(g_qk + ((size_t)b * H_ + (hg * 4 + j)) * E_ + eidx * 16);
#pragma unroll
        for (int i = 0; i < 4; i++) {
            float4 v = p[i];
            qk2[j][2 * i]     = pack2(v.x, v.y);
            qk2[j][2 * i + 1] = pack2(v.z, v.w);
        }
    }
    __syncthreads();

    for (int bat = 0; bat < 32; bat++) {
        int sb = s0 + bat * 4;
        // stage 4 rows (skip masked: stale data never read)
#pragma unroll
        for (int r = 0; r < 4; r++) {
            if (smask[bat * 4 + r]) {
                ((float4*)sx[r])[tid] =
                    ((const float4*)(seq2 + ((size_t)b * S_ + sb + r) * E_))[tid];
            }
        }
        __syncthreads();

        u64 acc[4][4];
#pragma unroll
        for (int r = 0; r < 4; r++)
#pragma unroll
            for (int j = 0; j < 4; j++) acc[r][j] = pack2(0.f, 0.f);

#pragma unroll
        for (int r = 0; r < 4; r++) {
            if (!smask[bat * 4 + r]) continue;
            const float4* xr = (const float4*)(sx[r] + eidx * 16);
#pragma unroll
            for (int i4 = 0; i4 < 4; i4++) {
                float4 xv = xr[i4];
                u64 x0 = pack2(xv.x, xv.y);
                u64 x1 = pack2(xv.z, xv.w);
#pragma unroll
                for (int j = 0; j < 4; j++) {
                    acc[r][j] = ffma2(qk2[j][2 * i4],     x0, acc[r][j]);
                    acc[r][j] = ffma2(qk2[j][2 * i4 + 1], x1, acc[r][j]);
                }
            }
        }
        // partial write: spart[r][h][eidx]
#pragma unroll
        for (int r = 0; r < 4; r++) {
#pragma unroll
            for (int j = 0; j < 4; j++) {
                float x, y;
                unpack2(acc[r][j], x, y);
                spart[r][hg * 4 + j][eidx] = x + y;
            }
        }
        __syncthreads();

        if (tid < 64) {
            int r = tid >> 4, h = tid & 15;
            const float4* p = (const float4*)&spart[r][h][0];
            float4 a0 = p[0], a1 = p[1], a2 = p[2], a3 = p[3];
#pragma unroll
            for (int i = 4; i < 16; i += 4) {
                float4 v0 = p[i], v1 = p[i + 1], v2 = p[i + 2], v3 = p[i + 3];
                a0.x += v0.x; a0.y += v0.y; a0.z += v0.z; a0.w += v0.w;
                a1.x += v1.x; a1.y += v1.y; a1.z += v1.z; a1.w += v1.w;
                a2.x += v2.x; a2.y += v2.y; a2.z += v2.z; a2.w += v2.w;
                a3.x += v3.x; a3.y += v3.y; a3.z += v3.z; a3.w += v3.w;
            }
            float s01 = (a0.x + a0.y) + (a0.z + a0.w);
            float s23 = (a1.x + a1.y) + (a1.z + a1.w);
            float s45 = (a2.x + a2.y) + (a2.z + a2.w);
            float s67 = (a3.x + a3.y) + (a3.z + a3.w);
            g_scores[((size_t)b * H_ + h) * S_ + sb + r] = (s01 + s23) + (s45 + s67);
        }
        __syncthreads();
    }
}

// ---------------- K4: softmax over s per (b,h), applying mask ----------------
// grid 512 block 256
__global__ void k_softmax(const int* __restrict__ mask) {
    int bh = blockIdx.x;
    int b = bh >> 4;
    int tid = threadIdx.x;
    const float* sc = g_scores + (size_t)bh * S_;
    const int* mk = mask + (size_t)b * S_;
    float* at = g_attn + (size_t)bh * S_;

    float x[16];
    float mx = -3.4e38f;
#pragma unroll
    for (int i = 0; i < 16; i++) {
        int s = i * 256 + tid;
        float v = (mk[s] != 0) ? sc[s] : -1e9f;
        x[i] = v;
        mx = fmaxf(mx, v);
    }
    __shared__ float red[8];
#pragma unroll
    for (int o = 16; o; o >>= 1) mx = fmaxf(mx, __shfl_xor_sync(0xffffffffu, mx, o));
    if ((tid & 31) == 0) red[tid >> 5] = mx;
    __syncthreads();
    mx = red[0];
#pragma unroll
    for (int w = 1; w < 8; w++) mx = fmaxf(mx, red[w]);
    __syncthreads();

    float sum = 0.f;
#pragma unroll
    for (int i = 0; i < 16; i++) {
        float e = __expf(x[i] - mx);
        x[i] = e;
        sum += e;
    }
#pragma unroll
    for (int o = 16; o; o >>= 1) sum += __shfl_xor_sync(0xffffffffu, sum, o);
    if ((tid & 31) == 0) red[tid >> 5] = sum;
    __syncthreads();
    sum = red[0];
#pragma unroll
    for (int w = 1; w < 8; w++) sum += red[w];
    float inv = 1.0f / sum;
#pragma unroll
    for (int i = 0; i < 16; i++) at[i * 256 + tid] = x[i] * inv;
}

// ---------------- K5: ctx partials: ctxp[sp][b][h][e] = Σ_{s in split} attn·seq2 ----------------
// grid (NSPLIT, 32 b) block 256, same (e_idx, h_grp) layout as K3
__global__ void __launch_bounds__(256, 2) k_ctx(const float* __restrict__ seq2,
                                                const int* __restrict__ mask) {
    int b = blockIdx.y;
    int split = blockIdx.x;
    int s0 = split * (S_ / NSPLIT);            // 256 rows per split
    int tid = threadIdx.x;
    int eidx = tid >> 2;
    int hg = tid & 3;

    __shared__ __align__(16) float sx[4][E_];         // 16 KB
    __shared__ __align__(16) float sa[H_][S_ / NSPLIT]; // 16 KB attn tile
    __shared__ int smask[S_ / NSPLIT];

    for (int i = tid; i < S_ / NSPLIT; i += 256) smask[i] = mask[b * S_ + s0 + i];
    for (int i = tid; i < H_ * (S_ / NSPLIT); i += 256) {
        int h = i >> 8, s = i & 255;
        sa[h][s] = g_attn[((size_t)b * H_ + h) * S_ + s0 + s];
    }
    __syncthreads();

    u64 ctx[4][8];
#pragma unroll
    for (int j = 0; j < 4; j++)
#pragma unroll
        for (int i = 0; i < 8; i++) ctx[j][i] = pack2(0.f, 0.f);

    for (int bat = 0; bat < (S_ / NSPLIT) / 4; bat++) {
#pragma unroll
        for (int r = 0; r < 4; r++) {
            if (smask[bat * 4 + r]) {
                ((float4*)sx[r])[tid] =
                    ((const float4*)(seq2 + ((size_t)b * S_ + s0 + bat * 4 + r) * E_))[tid];
            }
        }
        __syncthreads();
#pragma unroll
        for (int r = 0; r < 4; r++) {
            int sl = bat * 4 + r;
            if (!smask[sl]) continue;
            u64 w2[4];
#pragma unroll
            for (int j = 0; j < 4; j++) {
                float w = sa[hg * 4 + j][sl];
                w2[j] = pack2(w, w);
            }
            const float4* xr = (const float4*)(sx[r] + eidx * 16);
#pragma unroll
            for (int i4 = 0; i4 < 4; i4++) {
                float4 xv = xr[i4];
                u64 x0 = pack2(xv.x, xv.y);
                u64 x1 = pack2(xv.z, xv.w);
#pragma unroll
                for (int j = 0; j < 4; j++) {
                    ctx[j][2 * i4]     = ffma2(w2[j], x0, ctx[j][2 * i4]);
                    ctx[j][2 * i4 + 1] = ffma2(w2[j], x1, ctx[j][2 * i4 + 1]);
                }
            }
        }
        __syncthreads();
    }

    // write partial ctx: [sp][b][h][e]
#pragma unroll
    for (int j = 0; j < 4; j++) {
        float* dst = g_ctxp + (((size_t)split * B_ + b) * H_ + (hg * 4 + j)) * E_ + eidx * 16;
#pragma unroll
        for (int i = 0; i < 4; i++) {
            float x0, y0, x1, y1;
            unpack2(ctx[j][2 * i], x0, y0);
            unpack2(ctx[j][2 * i + 1], x1, y1);
            ((float4*)dst)[i] = make_float4(x0, y0, x1, y1);
        }
    }
}

// ---------------- K6: out[b][h*64+n] = Σ_e ctx[b][h][e]·Wv[e][h*64+n] + bv ----------------
// grid (16 h, 32 b) block 256; 4 threads per n, each 256 e
__global__ void k_out(const float* __restrict__ Wv, const float* __restrict__ bv,
                      float* __restrict__ out) {
    int h = blockIdx.x;
    int b = blockIdx.y;
    int tid = threadIdx.x;
    int n = tid & 63;
    int q = tid >> 6;

    __shared__ __align__(16) float sc[E_];
    // reduce ctx partials over splits while staging
    {
        float4 a = make_float4(0.f, 0.f, 0.f, 0.f);
#pragma unroll
        for (int sp = 0; sp < NSPLIT; sp++) {
            const float4* p =
                (const float4*)(g_ctxp + (((size_t)sp * B_ + b) * H_ + h) * E_);
            float4 v = p[tid];
            a.x += v.x; a.y += v.y; a.z += v.z; a.w += v.w;
        }
        ((float4*)sc)[tid] = a;
    }
    __syncthreads();

    int c = h * D_ + n;
    float acc = 0.f;
#pragma unroll 8
    for (int e = 0; e < 256; e++)
        acc = fmaf(sc[q * 256 + e], Wv[(size_t)(q * 256 + e) * E_ + c], acc);

    __shared__ float part[4][64];
    part[q][n] = acc;
    __syncthreads();
    if (tid < 64)
        out[(size_t)b * E_ + h * D_ + tid] =
            ((part[0][tid] + part[1][tid]) + (part[2][tid] + part[3][tid])) + bv[h * D_ + tid];
}

// ---------------- launch ----------------
extern "C" void kernel_launch(void* const* d_in, const int* in_sizes, int n_in,
                              void* d_out, int out_size) {
    const float* seq1 = (const float*)d_in[0];
    const float* seq2 = (const float*)d_in[1];
    const int*   mask = (const int*)d_in[2];
    const float* Wq   = (const float*)d_in[3];
    const float* bq   = (const float*)d_in[4];
    const float* Wk   = (const float*)d_in[5];
    // d_in[6] = bk: dropped (uniform shift over unmasked scores -> softmax-invariant)
    const float* Wv   = (const float*)d_in[7];
    const float* bv   = (const float*)d_in[8];
    float* out = (float*)d_out;

    k_qproj<<<dim3(4, B_), 256>>>(seq1, Wq, bq);
    k_qk<<<dim3(H_, 4), 256>>>(Wk);
    k_scores<<<dim3(S_ / 128, B_), 256>>>(seq2, mask);
    k_softmax<<<B_ * H_, 256>>>(mask);
    k_ctx<<<dim3(NSPLIT, B_), 256>>>(seq2, mask);
    k_out<<<dim3(H_, B_), 256>>>(Wv, bv, out);
}

// round 4
// speedup vs baseline: 1.3468x; 1.3468x over previous
#include <cuda_runtime.h>
#include <cstdint>
#include <cstddef>

#define B_ 32
#define S_ 4096
#define E_ 1024
#define H_ 16
#define D_ 64
#define NSPLIT 16

// ---------------- static scratch ----------------
__device__ float g_q[B_ * E_];
__device__ float g_qk[B_ * H_ * E_];
__device__ float g_scores[B_ * H_ * S_];
__device__ float g_attn[B_ * H_ * S_];
__device__ float g_ctxp[NSPLIT * B_ * H_ * E_];

typedef unsigned long long u64;

__device__ __forceinline__ u64 pack2(float x, float y) {
    u64 p;
    asm("mov.b64 %0, {%1, %2};" : "=l"(p) : "f"(x), "f"(y));
    return p;
}
__device__ __forceinline__ void unpack2(u64 p, float& x, float& y) {
    asm("mov.b64 {%0, %1}, %2;" : "=f"(x), "=f"(y) : "l"(p));
}
__device__ __forceinline__ u64 ffma2(u64 a, u64 b, u64 c) {
    u64 d;
    asm("fma.rn.f32x2 %0, %1, %2, %3;" : "=l"(d) : "l"(a), "l"(b), "l"(c));
    return d;
}
__device__ __forceinline__ void cp16(uint32_t dst_smem, const void* src) {
    asm volatile("cp.async.cg.shared.global [%0], [%1], 16;" ::
                 "r"(dst_smem), "l"(src));
}
__device__ __forceinline__ void cp_commit() {
    asm volatile("cp.async.commit_group;");
}
template <int N>
__device__ __forceinline__ void cp_wait() {
    asm volatile("cp.async.wait_group %0;" :: "n"(N));
}

// ---------------- K1: q = seq1@Wq + bq  (2 b per block) ----------------
// grid (4 jt, 16 bp) block 256
__global__ void k_qproj(const float* __restrict__ seq1, const float* __restrict__ Wq,
                        const float* __restrict__ bq) {
    int b0 = blockIdx.y * 2;
    int j = blockIdx.x * 256 + threadIdx.x;
    __shared__ __align__(16) float s1[2][E_];
    ((float4*)s1[0])[threadIdx.x] = ((const float4*)(seq1 + (size_t)b0 * E_))[threadIdx.x];
    ((float4*)s1[1])[threadIdx.x] = ((const float4*)(seq1 + (size_t)(b0 + 1) * E_))[threadIdx.x];
    __syncthreads();
    float a00 = 0.f, a01 = 0.f, a02 = 0.f, a03 = 0.f;
    float a10 = 0.f, a11 = 0.f, a12 = 0.f, a13 = 0.f;
#pragma unroll 4
    for (int e = 0; e < E_; e += 4) {
        float w0 = Wq[(size_t)(e + 0) * E_ + j];
        float w1 = Wq[(size_t)(e + 1) * E_ + j];
        float w2 = Wq[(size_t)(e + 2) * E_ + j];
        float w3 = Wq[(size_t)(e + 3) * E_ + j];
        a00 = fmaf(s1[0][e + 0], w0, a00);
        a01 = fmaf(s1[0][e + 1], w1, a01);
        a02 = fmaf(s1[0][e + 2], w2, a02);
        a03 = fmaf(s1[0][e + 3], w3, a03);
        a10 = fmaf(s1[1][e + 0], w0, a10);
        a11 = fmaf(s1[1][e + 1], w1, a11);
        a12 = fmaf(s1[1][e + 2], w2, a12);
        a13 = fmaf(s1[1][e + 3], w3, a13);
    }
    float bias = bq[j];
    g_q[b0 * E_ + j]       = ((a00 + a01) + (a02 + a03)) + bias;
    g_q[(b0 + 1) * E_ + j] = ((a10 + a11) + (a12 + a13)) + bias;
}

// ---------------- K2: qk[b][h][e] = (Σ_d q[b][h*64+d]·Wk[e][h*64+d]) * 0.125 ----------------
__global__ void k_qk(const float* __restrict__ Wk) {
    int h = blockIdx.x;
    int e = blockIdx.y * 256 + threadIdx.x;
    __shared__ __align__(16) float2 sq[B_][D_ / 2];
    for (int i = threadIdx.x; i < B_ * (D_ / 2); i += 256) {
        int b = i >> 5, dp = i & 31;
        sq[b][dp] = ((const float2*)(g_q + b * E_ + h * D_))[dp];
    }
    __syncthreads();
    float2 wk[D_ / 2];
    const float2* wrow = (const float2*)(Wk + (size_t)e * E_ + h * D_);
#pragma unroll
    for (int i = 0; i < D_ / 2; i++) wk[i] = wrow[i];
#pragma unroll 4
    for (int b = 0; b < B_; b++) {
        float ax = 0.f, ay = 0.f;
#pragma unroll
        for (int i = 0; i < D_ / 2; i++) {
            float2 qv = sq[b][i];
            ax = fmaf(wk[i].x, qv.x, ax);
            ay = fmaf(wk[i].y, qv.y, ay);
        }
        g_qk[(b * H_ + h) * E_ + e] = (ax + ay) * 0.125f;
    }
}

// ---------------- K3: scores (cp.async double-buffered) ----------------
// grid (32 s-tiles of 128, 32 b) block 256
// dynamic smem: sx[2][4][1024] (32KB) + spart[4*16*68] (17408B)
__global__ void __launch_bounds__(256, 2) k_scores(const float* __restrict__ seq2,
                                                   const int* __restrict__ mask) {
    extern __shared__ __align__(16) char dyn[];
    float* sx = (float*)dyn;                       // [2][4][1024]
    float* spart = (float*)(dyn + 32768);          // [rh=64][68]
    __shared__ uint32_t sball[4];

    int b = blockIdx.y;
    int s0 = blockIdx.x * 128;
    int tid = threadIdx.x;
    int wid = tid >> 5;
    int eidx = tid >> 2;
    int hg = tid & 3;

    if (wid < 4) {
        int m = mask[b * S_ + s0 + tid];
        uint32_t bal = __ballot_sync(0xffffffffu, m != 0);
        if ((tid & 31) == 0) sball[wid] = bal;
    }

    // qk regs: 4 heads x 16 e as 8 f32x2
    u64 qk2[4][8];
#pragma unroll
    for (int j = 0; j < 4; j++) {
        const float4* p = (const float4*)(g_qk + ((size_t)b * H_ + (hg * 4 + j)) * E_ + eidx * 16);
#pragma unroll
        for (int i = 0; i < 4; i++) {
            float4 v = p[i];
            qk2[j][2 * i]     = pack2(v.x, v.y);
            qk2[j][2 * i + 1] = pack2(v.z, v.w);
        }
    }
    __syncthreads();
    uint32_t mb0 = sball[0], mb1 = sball[1], mb2 = sball[2], mb3 = sball[3];

    uint32_t sx_addr = (uint32_t)__cvta_generic_to_shared(sx);
    const float* base = seq2 + ((size_t)b * S_ + s0) * E_;

    // stage batch 0
    {
        uint32_t fl = mb0 & 0xF;
#pragma unroll
        for (int r = 0; r < 4; r++)
            if ((fl >> r) & 1)
                cp16(sx_addr + r * 4096 + tid * 16, base + (size_t)r * E_ + tid * 4);
        cp_commit();
    }

    int buf = 0;
    for (int bat = 0; bat < 32; bat++) {
        if (bat < 31) {
            int nb = bat + 1;
            uint32_t mw = (nb < 8) ? mb0 : ((nb < 16) ? mb1 : ((nb < 24) ? mb2 : mb3));
            uint32_t fl = (mw >> ((nb & 7) * 4)) & 0xF;
            uint32_t dst = sx_addr + (buf ^ 1) * 16384 + tid * 16;
            const float* src = base + (size_t)nb * 4 * E_ + tid * 4;
#pragma unroll
            for (int r = 0; r < 4; r++)
                if ((fl >> r) & 1) cp16(dst + r * 4096, src + (size_t)r * E_);
            cp_commit();
            cp_wait<1>();
        } else {
            cp_wait<0>();
        }
        __syncthreads();

        uint32_t mw = (bat < 8) ? mb0 : ((bat < 16) ? mb1 : ((bat < 24) ? mb2 : mb3));
        uint32_t fl = (mw >> ((bat & 7) * 4)) & 0xF;

        u64 acc[4][4];
#pragma unroll
        for (int r = 0; r < 4; r++)
#pragma unroll
            for (int j = 0; j < 4; j++) acc[r][j] = pack2(0.f, 0.f);

#pragma unroll
        for (int r = 0; r < 4; r++) {
            if (!((fl >> r) & 1)) continue;
            const float4* xr = (const float4*)(sx + buf * 4096 + r * 1024 + eidx * 16);
#pragma unroll
            for (int i4 = 0; i4 < 4; i4++) {
                float4 xv = xr[i4];
                u64 x0 = pack2(xv.x, xv.y);
                u64 x1 = pack2(xv.z, xv.w);
#pragma unroll
                for (int j = 0; j < 4; j++) {
                    acc[r][j] = ffma2(qk2[j][2 * i4],     x0, acc[r][j]);
                    acc[r][j] = ffma2(qk2[j][2 * i4 + 1], x1, acc[r][j]);
                }
            }
        }
#pragma unroll
        for (int r = 0; r < 4; r++)
#pragma unroll
            for (int j = 0; j < 4; j++) {
                float x, y;
                unpack2(acc[r][j], x, y);
                spart[(r * 16 + hg * 4 + j) * 68 + eidx] = x + y;
            }
        __syncthreads();

        // reduction: all 256 threads; thread -> (rh, quarter q)
        {
            int rh = tid >> 2, q = tid & 3;
            const float4* p = (const float4*)(spart + rh * 68 + q * 16);
            float4 v0 = p[0], v1 = p[1], v2 = p[2], v3 = p[3];
            float s = (((v0.x + v0.y) + (v0.z + v0.w)) + ((v1.x + v1.y) + (v1.z + v1.w))) +
                      (((v2.x + v2.y) + (v2.z + v2.w)) + ((v3.x + v3.y) + (v3.z + v3.w)));
            s += __shfl_xor_sync(0xffffffffu, s, 1);
            s += __shfl_xor_sync(0xffffffffu, s, 2);
            if (q == 0) {
                int r = rh >> 4, h = rh & 15;
                g_scores[((size_t)b * H_ + h) * S_ + s0 + bat * 4 + r] = s;
            }
        }
        buf ^= 1;
    }
}

// ---------------- K4: softmax ----------------
__global__ void k_softmax(const int* __restrict__ mask) {
    int bh = blockIdx.x;
    int b = bh >> 4;
    int tid = threadIdx.x;
    const float* sc = g_scores + (size_t)bh * S_;
    const int* mk = mask + (size_t)b * S_;
    float* at = g_attn + (size_t)bh * S_;

    float x[16];
    float mx = -3.4e38f;
#pragma unroll
    for (int i = 0; i < 16; i++) {
        int s = i * 256 + tid;
        float v = (mk[s] != 0) ? sc[s] : -1e9f;
        x[i] = v;
        mx = fmaxf(mx, v);
    }
    __shared__ float red[8];
#pragma unroll
    for (int o = 16; o; o >>= 1) mx = fmaxf(mx, __shfl_xor_sync(0xffffffffu, mx, o));
    if ((tid & 31) == 0) red[tid >> 5] = mx;
    __syncthreads();
    mx = red[0];
#pragma unroll
    for (int w = 1; w < 8; w++) mx = fmaxf(mx, red[w]);
    __syncthreads();

    float sum = 0.f;
#pragma unroll
    for (int i = 0; i < 16; i++) {
        float e = __expf(x[i] - mx);
        x[i] = e;
        sum += e;
    }
#pragma unroll
    for (int o = 16; o; o >>= 1) sum += __shfl_xor_sync(0xffffffffu, sum, o);
    if ((tid & 31) == 0) red[tid >> 5] = sum;
    __syncthreads();
    sum = red[0];
#pragma unroll
    for (int w = 1; w < 8; w++) sum += red[w];
    float inv = 1.0f / sum;
#pragma unroll
    for (int i = 0; i < 16; i++) at[i * 256 + tid] = x[i] * inv;
}

// ---------------- K5: ctx partials (cp.async double-buffered) ----------------
// grid (NSPLIT, 32 b) block 256
// dynamic smem: sx[2][4][1024] (32KB) + sa[16][256] (16KB)
__global__ void __launch_bounds__(256, 2) k_ctx(const float* __restrict__ seq2,
                                                const int* __restrict__ mask) {
    extern __shared__ __align__(16) char dyn[];
    float* sx = (float*)dyn;               // [2][4][1024]
    float* sa = (float*)(dyn + 32768);     // [16][256]
    __shared__ uint32_t sball[8];

    int b = blockIdx.y;
    int split = blockIdx.x;
    int s0 = split * 256;
    int tid = threadIdx.x;
    int wid = tid >> 5;
    int eidx = tid >> 2;
    int hg = tid & 3;

    {
        int m = mask[b * S_ + s0 + tid];
        uint32_t bal = __ballot_sync(0xffffffffu, m != 0);
        if ((tid & 31) == 0) sball[wid] = bal;
    }
    for (int i = tid; i < H_ * 256; i += 256) {
        int h = i >> 8, s = i & 255;
        sa[h * 256 + s] = g_attn[((size_t)b * H_ + h) * S_ + s0 + s];
    }
    __syncthreads();
    uint32_t mb[8];
#pragma unroll
    for (int w = 0; w < 8; w++) mb[w] = sball[w];

    uint32_t sx_addr = (uint32_t)__cvta_generic_to_shared(sx);
    const float* base = seq2 + ((size_t)b * S_ + s0) * E_;

    u64 ctx[4][8];
#pragma unroll
    for (int j = 0; j < 4; j++)
#pragma unroll
        for (int i = 0; i < 8; i++) ctx[j][i] = pack2(0.f, 0.f);

    // stage batch 0
    {
        uint32_t fl = mb[0] & 0xF;
#pragma unroll
        for (int r = 0; r < 4; r++)
            if ((fl >> r) & 1)
                cp16(sx_addr + r * 4096 + tid * 16, base + (size_t)r * E_ + tid * 4);
        cp_commit();
    }

    int buf = 0;
    for (int bat = 0; bat < 64; bat++) {
        if (bat < 63) {
            int nb = bat + 1;
            uint32_t fl = (mb[nb >> 3] >> ((nb & 7) * 4)) & 0xF;
            uint32_t dst = sx_addr + (buf ^ 1) * 16384 + tid * 16;
            const float* src = base + (size_t)nb * 4 * E_ + tid * 4;
#pragma unroll
            for (int r = 0; r < 4; r++)
                if ((fl >> r) & 1) cp16(dst + r * 4096, src + (size_t)r * E_);
            cp_commit();
            cp_wait<1>();
        } else {
            cp_wait<0>();
        }
        __syncthreads();

        uint32_t fl = (mb[bat >> 3] >> ((bat & 7) * 4)) & 0xF;
#pragma unroll
        for (int r = 0; r < 4; r++) {
            if (!((fl >> r) & 1)) continue;
            int sl = bat * 4 + r;
            u64 w2[4];
#pragma unroll
            for (int j = 0; j < 4; j++) {
                float w = sa[(hg * 4 + j) * 256 + sl];
                w2[j] = pack2(w, w);
            }
            const float4* xr = (const float4*)(sx + buf * 4096 + r * 1024 + eidx * 16);
#pragma unroll
            for (int i4 = 0; i4 < 4; i4++) {
                float4 xv = xr[i4];
                u64 x0 = pack2(xv.x, xv.y);
                u64 x1 = pack2(xv.z, xv.w);
#pragma unroll
                for (int j = 0; j < 4; j++) {
                    ctx[j][2 * i4]     = ffma2(w2[j], x0, ctx[j][2 * i4]);
                    ctx[j][2 * i4 + 1] = ffma2(w2[j], x1, ctx[j][2 * i4 + 1]);
                }
            }
        }
        __syncthreads();
        buf ^= 1;
    }

#pragma unroll
    for (int j = 0; j < 4; j++) {
        float* dst = g_ctxp + (((size_t)split * B_ + b) * H_ + (hg * 4 + j)) * E_ + eidx * 16;
#pragma unroll
        for (int i = 0; i < 4; i++) {
            float x0, y0, x1, y1;
            unpack2(ctx[j][2 * i], x0, y0);
            unpack2(ctx[j][2 * i + 1], x1, y1);
            ((float4*)dst)[i] = make_float4(x0, y0, x1, y1);
        }
    }
}

// ---------------- K6: out = ctx@Wv + bv  (4 b per block) ----------------
// grid (16 h, 8 bg) block 256
__global__ void k_out(const float* __restrict__ Wv, const float* __restrict__ bv,
                      float* __restrict__ out) {
    int h = blockIdx.x;
    int b0 = blockIdx.y * 4;
    int tid = threadIdx.x;
    int n = tid & 63;
    int q = tid >> 6;

    __shared__ __align__(16) float sc[4][E_];
#pragma unroll
    for (int bb = 0; bb < 4; bb++) {
        float4 a = make_float4(0.f, 0.f, 0.f, 0.f);
#pragma unroll
        for (int sp = 0; sp < NSPLIT; sp++) {
            float4 v = ((const float4*)(g_ctxp + (((size_t)sp * B_ + b0 + bb) * H_ + h) * E_))[tid];
            a.x += v.x; a.y += v.y; a.z += v.z; a.w += v.w;
        }
        ((float4*)sc[bb])[tid] = a;
    }
    __syncthreads();

    int c = h * D_ + n;
    float a0 = 0.f, a1 = 0.f, a2 = 0.f, a3 = 0.f;
#pragma unroll 4
    for (int e = 0; e < 256; e++) {
        float w = Wv[(size_t)(q * 256 + e) * E_ + c];
        a0 = fmaf(sc[0][q * 256 + e], w, a0);
        a1 = fmaf(sc[1][q * 256 + e], w, a1);
        a2 = fmaf(sc[2][q * 256 + e], w, a2);
        a3 = fmaf(sc[3][q * 256 + e], w, a3);
    }
    __shared__ float part[4][4][64];
    part[0][q][n] = a0;
    part[1][q][n] = a1;
    part[2][q][n] = a2;
    part[3][q][n] = a3;
    __syncthreads();
    if (tid < 256) {
        int bb = tid >> 6, nn = tid & 63;
        float s = ((part[bb][0][nn] + part[bb][1][nn]) + (part[bb][2][nn] + part[bb][3][nn]));
        out[(size_t)(b0 + bb) * E_ + h * D_ + nn] = s + bv[h * D_ + nn];
    }
}

// ---------------- launch ----------------
extern "C" void kernel_launch(void* const* d_in, const int* in_sizes, int n_in,
                              void* d_out, int out_size) {
    const float* seq1 = (const float*)d_in[0];
    const float* seq2 = (const float*)d_in[1];
    const int*   mask = (const int*)d_in[2];
    const float* Wq   = (const float*)d_in[3];
    const float* bq   = (const float*)d_in[4];
    const float* Wk   = (const float*)d_in[5];
    // d_in[6] = bk dropped (softmax-invariant uniform shift)
    const float* Wv   = (const float*)d_in[7];
    const float* bv   = (const float*)d_in[8];
    float* out = (float*)d_out;

    static int attr_done = 0;
    // setting attributes is idempotent & capture-safe (no graph nodes)
    cudaFuncSetAttribute(k_scores, cudaFuncAttributeMaxDynamicSharedMemorySize, 32768 + 17408);
    cudaFuncSetAttribute(k_ctx, cudaFuncAttributeMaxDynamicSharedMemorySize, 32768 + 16384);
    (void)attr_done;

    k_qproj<<<dim3(4, 16), 256>>>(seq1, Wq, bq);
    k_qk<<<dim3(H_, 4), 256>>>(Wk);
    k_scores<<<dim3(S_ / 128, B_), 256, 32768 + 17408>>>(seq2, mask);
    k_softmax<<<B_ * H_, 256>>>(mask);
    k_ctx<<<dim3(NSPLIT, B_), 256, 32768 + 16384>>>(seq2, mask);
    k_out<<<dim3(H_, 8), 256>>>(Wv, bv, out);
}